// round 3
// baseline (speedup 1.0000x reference)
#include <cuda_runtime.h>
#include <cstdint>

// Problem constants
#define BDIM  32
#define TP    1024          // reduced sequence length (T/RED)
#define INF   1024          // input features after reduction (D*RED)
#define HID   512
#define G4    2048          // 4*H
#define PDIM  512
#define MROWS (BDIM * TP)   // 32768

// Time chunking: recurrence processed in NCH chunks of CHUNK steps
#define CHUNK 128
#define NCH   (TP / CHUNK)
#define CHSTRIDE ((size_t)CHUNK * BDIM * G4)   // floats per dir per chunk

// ---------------------------------------------------------------------------
// Device scratch (static; total ~202 MB)
// ---------------------------------------------------------------------------
// x-gates for ONE chunk, layout [dir][sloc][b][g]; dir=1 rows are gathered by
// scan index s (A row t = len_b-1-s), so both scans read at chunk-local sloc.
__device__ float g_xg[2 * CHSTRIDE];                        // 67 MB
// hidden state per dir, transposed layout: index = (u>>2)*128 + b*4 + (u&3)
__device__ float g_hbuf[2 * HID * BDIM];                    // 128 KB
// cell state per dir: index = dir*16384 + ug*32 + b
__device__ float g_cbuf[2 * HID * BDIM];                    // 128 KB
// LSTM outputs [b][t][1024]  (cols 0..511 = fwd, 512..1023 = rev)
__device__ float g_out[(size_t)MROWS * 1024];               // 134 MB
__device__ unsigned g_bar;

// ---------------------------------------------------------------------------
__global__ void zero_scratch() {
    size_t idx = (size_t)blockIdx.x * blockDim.x + threadIdx.x;
    size_t stride = (size_t)gridDim.x * blockDim.x;
    for (size_t i = idx; i < (size_t)MROWS * 1024; i += stride) g_out[i] = 0.0f;
    for (size_t i = idx; i < (size_t)2 * HID * BDIM; i += stride) {
        g_hbuf[i] = 0.0f;
        g_cbuf[i] = 0.0f;
    }
    if (idx == 0) g_bar = 0u;
}

// ---------------------------------------------------------------------------
// Kernel 1: x-gates GEMM for one chunk (both directions).
//   C[m=(b,sloc)][n=(dir,g)] = A_row(b, dir, s) . W_dir[g] + b_ih + b_hh
//   dir=0: A row t = c*CHUNK + sloc;  dir=1: A row t = len_b-1-s (clamped).
// Each m-tile covers a single batch b (128 rows = 128 sloc values).
// 128x128x8 tile, 8x8 per thread.
// ---------------------------------------------------------------------------
__global__ void __launch_bounds__(256) gates_gemm(
    const float* __restrict__ A,
    const float* __restrict__ w_f, const float* __restrict__ w_r,
    const float* __restrict__ bihf, const float* __restrict__ bhhf,
    const float* __restrict__ bihr, const float* __restrict__ bhhr,
    const int* __restrict__ sizes, int chunk)
{
    __shared__ float As[8][128];
    __shared__ float Bs[8][128];

    const int n0  = blockIdx.x * 128;         // 0..4095
    const int b   = blockIdx.y;               // batch (one per m-tile)
    const int dir = n0 >> 11;
    const float* __restrict__ W = dir ? w_r : w_f;
    const int gbase = n0 & 2047;
    const int len = sizes[b] >> 1;

    const int tid  = threadIdx.x;
    const int lrow = tid >> 1;                // 0..127
    const int lk4  = (tid & 1) << 2;          // 0 or 4

    // A row for this thread: chunk-local sloc = lrow
    int s = chunk * CHUNK + lrow;
    int t = dir ? (len - 1 - s) : s;
    if (t < 0) t = 0;                          // masked later; just stay in-bounds
    const float* Ap = A + ((size_t)b * TP + t) * INF + lk4;
    const float* Wp = W + (size_t)(gbase + lrow) * INF + lk4;

    const int tx = tid & 15, ty = tid >> 4;

    float acc[8][8];
#pragma unroll
    for (int i = 0; i < 8; i++)
#pragma unroll
        for (int j = 0; j < 8; j++) acc[i][j] = 0.0f;

    float4 av = *(const float4*)Ap;
    float4 bv = *(const float4*)Wp;

    for (int k0 = 0; k0 < INF; k0 += 8) {
        As[lk4 + 0][lrow] = av.x; As[lk4 + 1][lrow] = av.y;
        As[lk4 + 2][lrow] = av.z; As[lk4 + 3][lrow] = av.w;
        Bs[lk4 + 0][lrow] = bv.x; Bs[lk4 + 1][lrow] = bv.y;
        Bs[lk4 + 2][lrow] = bv.z; Bs[lk4 + 3][lrow] = bv.w;
        __syncthreads();
        if (k0 + 8 < INF) {
            av = *(const float4*)(Ap + k0 + 8);
            bv = *(const float4*)(Wp + k0 + 8);
        }
#pragma unroll
        for (int k = 0; k < 8; k++) {
            float a[8], bb[8];
            *(float4*)(a)      = *(const float4*)&As[k][ty * 8];
            *(float4*)(a + 4)  = *(const float4*)&As[k][ty * 8 + 4];
            *(float4*)(bb)     = *(const float4*)&Bs[k][tx * 8];
            *(float4*)(bb + 4) = *(const float4*)&Bs[k][tx * 8 + 4];
#pragma unroll
            for (int i = 0; i < 8; i++)
#pragma unroll
                for (int j = 0; j < 8; j++)
                    acc[i][j] = fmaf(a[i], bb[j], acc[i][j]);
        }
        __syncthreads();
    }

    const float* __restrict__ bih = dir ? bihr : bihf;
    const float* __restrict__ bhh = dir ? bhhr : bhhf;
    const int gcol = gbase + tx * 8;
    float bias[8];
#pragma unroll
    for (int j = 0; j < 8; j++) bias[j] = bih[gcol + j] + bhh[gcol + j];

    float* base = g_xg + (size_t)dir * CHSTRIDE;
#pragma unroll
    for (int i = 0; i < 8; i++) {
        int sloc = ty * 8 + i;
        float* dst = base + ((size_t)sloc * BDIM + b) * G4 + gcol;
        float4 v0, v1;
        v0.x = acc[i][0] + bias[0]; v0.y = acc[i][1] + bias[1];
        v0.z = acc[i][2] + bias[2]; v0.w = acc[i][3] + bias[3];
        v1.x = acc[i][4] + bias[4]; v1.y = acc[i][5] + bias[5];
        v1.z = acc[i][6] + bias[6]; v1.w = acc[i][7] + bias[7];
        *(float4*)dst       = v0;
        *(float4*)(dst + 4) = v1;
    }
}

// ---------------------------------------------------------------------------
// Kernel 2: persistent bidirectional LSTM recurrence for one chunk.
// 128 CTAs x 256 threads, 1 CTA/SM (135 KB smem), single wave on 148 SMs.
// CTAs 0..63 -> forward (8 hidden units each), 64..127 -> reverse.
// W_hh slice in smem; c-state persisted in g_cbuf across chunk launches;
// h exchanged via g_hbuf each step with a global atomic barrier.
// ---------------------------------------------------------------------------
#define RCTAS 128
#define UPC   8
#define SMEM_REC ((16384 + 16384 + 8 * 132) * 4)

__device__ __forceinline__ void grid_bar(unsigned target) {
    __syncthreads();
    if (threadIdx.x == 0) {
        __threadfence();
        atomicAdd(&g_bar, 1u);
        while (*((volatile unsigned*)&g_bar) < target) __nanosleep(64);
        __threadfence();
    }
    __syncthreads();
}

__device__ __forceinline__ float sigf(float x) {
    return 1.0f / (1.0f + __expf(-x));
}

__global__ void __launch_bounds__(256, 1) lstm_recur(
    const float* __restrict__ whh_f, const float* __restrict__ whh_r,
    const int* __restrict__ sizes, int chunk)
{
    extern __shared__ float sm[];
    float* w_s = sm;                 // [UPC][4][512]          16384 floats
    float* h_s = sm + 16384;         // [kc=128][b=32][4]      16384 floats
    float* x_s = sm + 32768;         // [UPC][132] staging / exchange

    const int cta = blockIdx.x;
    const int dir = cta >> 6;
    const int u0  = (cta & 63) * UPC;
    const float* __restrict__ Whh = dir ? whh_r : whh_f;

    const int tid  = threadIdx.x;
    const int warp = tid >> 5, lane = tid & 31;

    // Load persistent W_hh slice: w_s[u][gate][k], g = gate*512 + (u0+u)
    for (int i = tid; i < 4096; i += 256) {
        int idx = i << 2;
        int u    = idx >> 11;
        int rem  = idx & 2047;
        int gate = rem >> 9;
        int k    = rem & 511;
        *(float4*)(w_s + idx) =
            *(const float4*)(Whh + ((size_t)(gate * 512 + u0 + u)) * HID + k);
    }

    const int mylen = sizes[lane] >> 1;   // lane == batch in pointwise phase
    const int gate = lane >> 3;
    const int b0   = (lane & 7) << 2;
    const float* wrow = w_s + (warp * 4 + gate) * 512;
    const float* xgbase = g_xg + (size_t)dir * CHSTRIDE;
    float* hglob = g_hbuf + dir * 16384;
    const int ug = u0 + warp;

    // persisted cell state for cell (ug, lane)
    float c_state = g_cbuf[dir * 16384 + ug * 32 + lane];

    __syncthreads();   // w_s ready

    for (int sloc = 0; sloc < CHUNK; ++sloc) {
        const int s = chunk * CHUNK + sloc;

        // cooperative load of full h (same layout copy)
        {
            const float4* src = (const float4*)hglob;
            float4* dst = (float4*)h_s;
#pragma unroll
            for (int i = 0; i < 16; i++) dst[tid + i * 256] = src[tid + i * 256];
        }
        // stage this CTA's x-gate slice: x_s[u][gate*33 + b]
        if (tid < 128) {
            int b = tid >> 2, gt = tid & 3;
            const float* p = xgbase + ((size_t)sloc * BDIM + b) * G4 + gt * 512 + u0;
            float4 v0 = *(const float4*)p;
            float4 v1 = *(const float4*)(p + 4);
            x_s[0 * 132 + gt * 33 + b] = v0.x;
            x_s[1 * 132 + gt * 33 + b] = v0.y;
            x_s[2 * 132 + gt * 33 + b] = v0.z;
            x_s[3 * 132 + gt * 33 + b] = v0.w;
            x_s[4 * 132 + gt * 33 + b] = v1.x;
            x_s[5 * 132 + gt * 33 + b] = v1.y;
            x_s[6 * 132 + gt * 33 + b] = v1.z;
            x_s[7 * 132 + gt * 33 + b] = v1.w;
        }
        __syncthreads();

        // matmul phase: lane computes gate `gate` for batches b0..b0+3 of unit ug
        float a0 = x_s[warp * 132 + gate * 33 + b0 + 0];
        float a1 = x_s[warp * 132 + gate * 33 + b0 + 1];
        float a2 = x_s[warp * 132 + gate * 33 + b0 + 2];
        float a3 = x_s[warp * 132 + gate * 33 + b0 + 3];
#pragma unroll 8
        for (int kc = 0; kc < 128; kc++) {
            float4 w4 = *(const float4*)(wrow + kc * 4);
            const float* hb = h_s + kc * 128;
            float4 h0 = *(const float4*)(hb + (b0 + 0) * 4);
            float4 h1 = *(const float4*)(hb + (b0 + 1) * 4);
            float4 h2 = *(const float4*)(hb + (b0 + 2) * 4);
            float4 h3 = *(const float4*)(hb + (b0 + 3) * 4);
            a0 = fmaf(w4.x, h0.x, a0); a1 = fmaf(w4.x, h1.x, a1);
            a2 = fmaf(w4.x, h2.x, a2); a3 = fmaf(w4.x, h3.x, a3);
            a0 = fmaf(w4.y, h0.y, a0); a1 = fmaf(w4.y, h1.y, a1);
            a2 = fmaf(w4.y, h2.y, a2); a3 = fmaf(w4.y, h3.y, a3);
            a0 = fmaf(w4.z, h0.z, a0); a1 = fmaf(w4.z, h1.z, a1);
            a2 = fmaf(w4.z, h2.z, a2); a3 = fmaf(w4.z, h3.z, a3);
            a0 = fmaf(w4.w, h0.w, a0); a1 = fmaf(w4.w, h1.w, a1);
            a2 = fmaf(w4.w, h2.w, a2); a3 = fmaf(w4.w, h3.w, a3);
        }

        // gate exchange within warp (reuse this warp's private x_s row)
        float* ex = x_s + warp * 132;
        ex[gate * 32 + b0 + 0] = a0;
        ex[gate * 32 + b0 + 1] = a1;
        ex[gate * 32 + b0 + 2] = a2;
        ex[gate * 32 + b0 + 3] = a3;
        __syncwarp();

        // pointwise phase: lane == batch b, cell (ug, lane)
        float xi = ex[0 * 32 + lane];
        float xf = ex[1 * 32 + lane];
        float xg = ex[2 * 32 + lane];
        float xo = ex[3 * 32 + lane];

        if (s < mylen) {
            float i_ = sigf(xi);
            float f_ = sigf(xf);
            float gg = tanhf(xg);
            float o_ = sigf(xo);
            c_state = f_ * c_state + i_ * gg;
            float hnew = o_ * tanhf(c_state);
            hglob[(ug >> 2) * 128 + lane * 4 + (ug & 3)] = hnew;
            int tout = dir ? (mylen - 1 - s) : s;
            g_out[((size_t)lane * TP + tout) * 1024 + dir * 512 + ug] = hnew;
        }

        grid_bar((unsigned)(chunk * CHUNK + sloc + 1) * RCTAS);
    }

    // persist cell state for next chunk
    g_cbuf[dir * 16384 + ug * 32 + lane] = c_state;
}

// ---------------------------------------------------------------------------
// Kernel 3: projection GEMM  out[m][p] = tanh( g_out[m][:] . proj_w[p][:] + pb )
// ---------------------------------------------------------------------------
__global__ void __launch_bounds__(256) proj_gemm(
    const float* __restrict__ Wp_, const float* __restrict__ pb,
    float* __restrict__ out)
{
    __shared__ float As[8][128];
    __shared__ float Bs[8][128];

    const int n0 = blockIdx.x * 128;          // P=512 -> 4 tiles
    const int m0 = blockIdx.y * 128;

    const int tid  = threadIdx.x;
    const int lrow = tid >> 1;
    const int lk4  = (tid & 1) << 2;
    const float* Ap = g_out + (size_t)(m0 + lrow) * 1024 + lk4;
    const float* Wp = Wp_ + (size_t)(n0 + lrow) * 1024 + lk4;

    const int tx = tid & 15, ty = tid >> 4;

    float acc[8][8];
#pragma unroll
    for (int i = 0; i < 8; i++)
#pragma unroll
        for (int j = 0; j < 8; j++) acc[i][j] = 0.0f;

    float4 av = *(const float4*)Ap;
    float4 bv = *(const float4*)Wp;

    for (int k0 = 0; k0 < 1024; k0 += 8) {
        As[lk4 + 0][lrow] = av.x; As[lk4 + 1][lrow] = av.y;
        As[lk4 + 2][lrow] = av.z; As[lk4 + 3][lrow] = av.w;
        Bs[lk4 + 0][lrow] = bv.x; Bs[lk4 + 1][lrow] = bv.y;
        Bs[lk4 + 2][lrow] = bv.z; Bs[lk4 + 3][lrow] = bv.w;
        __syncthreads();
        if (k0 + 8 < 1024) {
            av = *(const float4*)(Ap + k0 + 8);
            bv = *(const float4*)(Wp + k0 + 8);
        }
#pragma unroll
        for (int k = 0; k < 8; k++) {
            float a[8], bb[8];
            *(float4*)(a)      = *(const float4*)&As[k][ty * 8];
            *(float4*)(a + 4)  = *(const float4*)&As[k][ty * 8 + 4];
            *(float4*)(bb)     = *(const float4*)&Bs[k][tx * 8];
            *(float4*)(bb + 4) = *(const float4*)&Bs[k][tx * 8 + 4];
#pragma unroll
            for (int i = 0; i < 8; i++)
#pragma unroll
                for (int j = 0; j < 8; j++)
                    acc[i][j] = fmaf(a[i], bb[j], acc[i][j]);
        }
        __syncthreads();
    }

    const int pcol = n0 + tx * 8;
    float bias[8];
#pragma unroll
    for (int j = 0; j < 8; j++) bias[j] = pb[pcol + j];

#pragma unroll
    for (int i = 0; i < 8; i++) {
        int m = m0 + ty * 8 + i;
        float* dst = out + (size_t)m * PDIM + pcol;
        float4 v0, v1;
        v0.x = tanhf(acc[i][0] + bias[0]); v0.y = tanhf(acc[i][1] + bias[1]);
        v0.z = tanhf(acc[i][2] + bias[2]); v0.w = tanhf(acc[i][3] + bias[3]);
        v1.x = tanhf(acc[i][4] + bias[4]); v1.y = tanhf(acc[i][5] + bias[5]);
        v1.z = tanhf(acc[i][6] + bias[6]); v1.w = tanhf(acc[i][7] + bias[7]);
        *(float4*)dst       = v0;
        *(float4*)(dst + 4) = v1;
    }
}

// Optional second output: lens = input_size // 2 (if harness flattens the tuple)
__global__ void lens_tail(const int* __restrict__ sizes, float* __restrict__ out,
                          int extra) {
    int i = threadIdx.x;
    if (i < extra && i < BDIM)
        out[(size_t)MROWS * PDIM + i] = (float)(sizes[i] >> 1);
}

// ---------------------------------------------------------------------------
extern "C" void kernel_launch(void* const* d_in, const int* in_sizes, int n_in,
                              void* d_out, int out_size) {
    const float* x    = (const float*)d_in[0];
    const int*   sz   = (const int*)d_in[1];
    const float* wihf = (const float*)d_in[2];
    const float* whhf = (const float*)d_in[3];
    const float* bihf = (const float*)d_in[4];
    const float* bhhf = (const float*)d_in[5];
    const float* wihr = (const float*)d_in[6];
    const float* whhr = (const float*)d_in[7];
    const float* bihr = (const float*)d_in[8];
    const float* bhhr = (const float*)d_in[9];
    const float* pw   = (const float*)d_in[10];
    const float* pbv  = (const float*)d_in[11];
    float* out = (float*)d_out;

    cudaFuncSetAttribute(lstm_recur, cudaFuncAttributeMaxDynamicSharedMemorySize,
                         SMEM_REC);

    zero_scratch<<<512, 256>>>();
    for (int c = 0; c < NCH; ++c) {
        gates_gemm<<<dim3(32, 32), 256>>>(x, wihf, wihr, bihf, bhhf, bihr, bhhr,
                                          sz, c);
        lstm_recur<<<RCTAS, 256, SMEM_REC>>>(whhf, whhr, sz, c);
    }
    proj_gemm<<<dim3(4, 256), 256>>>(pw, pbv, out);

    long long extra = (long long)out_size - (long long)MROWS * PDIM;
    if (extra > 0) lens_tail<<<1, 32>>>(sz, out, (int)extra);
}

// round 4
// speedup vs baseline: 1.0029x; 1.0029x over previous
#include <cuda_runtime.h>
#include <cstdint>

// Problem constants
#define BDIM  32
#define TP    1024          // reduced sequence length (T/RED)
#define INF   1024          // input features after reduction (D*RED)
#define HID   512
#define G4    2048          // 4*H
#define PDIM  512
#define MROWS (BDIM * TP)   // 32768

// Time chunking: recurrence processed in NCH chunks of CHUNK steps
#define CHUNK 128
#define NCH   (TP / CHUNK)
#define CHSTRIDE ((size_t)CHUNK * BDIM * G4)   // floats per dir per chunk

// ---------------------------------------------------------------------------
// Device scratch (static; total ~202 MB)
// ---------------------------------------------------------------------------
// x-gates for ONE chunk, layout [dir][sloc][b][g]; dir=1 rows are gathered by
// scan index s (A row t = len_b-1-s), so both scans read at chunk-local sloc.
__device__ float g_xg[2 * CHSTRIDE];                        // 67 MB
// hidden state per dir, transposed layout: index = (u>>2)*128 + b*4 + (u&3)
__device__ float g_hbuf[2 * HID * BDIM];                    // 128 KB
// cell state per dir: index = dir*16384 + ug*32 + b
__device__ float g_cbuf[2 * HID * BDIM];                    // 128 KB
// LSTM outputs [b][t][1024]  (cols 0..511 = fwd, 512..1023 = rev)
__device__ float g_out[(size_t)MROWS * 1024];               // 134 MB
__device__ unsigned g_bar;

// ---------------------------------------------------------------------------
__global__ void zero_scratch() {
    size_t idx = (size_t)blockIdx.x * blockDim.x + threadIdx.x;
    size_t stride = (size_t)gridDim.x * blockDim.x;
    for (size_t i = idx; i < (size_t)MROWS * 1024; i += stride) g_out[i] = 0.0f;
    for (size_t i = idx; i < (size_t)2 * HID * BDIM; i += stride) {
        g_hbuf[i] = 0.0f;
        g_cbuf[i] = 0.0f;
    }
    if (idx == 0) g_bar = 0u;
}

// ---------------------------------------------------------------------------
// Kernel 1: x-gates GEMM for one chunk (both directions).
//   C[m=(b,sloc)][n=(dir,g)] = A_row(b, dir, s) . W_dir[g] + b_ih + b_hh
//   dir=0: A row t = c*CHUNK + sloc;  dir=1: A row t = len_b-1-s (clamped).
// Each m-tile covers a single batch b (128 rows = 128 sloc values).
// 128x128x8 tile, 8x8 per thread.
// ---------------------------------------------------------------------------
__global__ void __launch_bounds__(256) gates_gemm(
    const float* __restrict__ A,
    const float* __restrict__ w_f, const float* __restrict__ w_r,
    const float* __restrict__ bihf, const float* __restrict__ bhhf,
    const float* __restrict__ bihr, const float* __restrict__ bhhr,
    const int* __restrict__ sizes, int chunk)
{
    __shared__ float As[8][128];
    __shared__ float Bs[8][128];

    const int n0  = blockIdx.x * 128;         // 0..4095
    const int b   = blockIdx.y;               // batch (one per m-tile)
    const int dir = n0 >> 11;
    const float* __restrict__ W = dir ? w_r : w_f;
    const int gbase = n0 & 2047;
    const int len = sizes[b] >> 1;

    const int tid  = threadIdx.x;
    const int lrow = tid >> 1;                // 0..127
    const int lk4  = (tid & 1) << 2;          // 0 or 4

    // A row for this thread: chunk-local sloc = lrow
    int s = chunk * CHUNK + lrow;
    int t = dir ? (len - 1 - s) : s;
    if (t < 0) t = 0;                          // masked later; just stay in-bounds
    const float* Ap = A + ((size_t)b * TP + t) * INF + lk4;
    const float* Wp = W + (size_t)(gbase + lrow) * INF + lk4;

    const int tx = tid & 15, ty = tid >> 4;

    float acc[8][8];
#pragma unroll
    for (int i = 0; i < 8; i++)
#pragma unroll
        for (int j = 0; j < 8; j++) acc[i][j] = 0.0f;

    float4 av = *(const float4*)Ap;
    float4 bv = *(const float4*)Wp;

    for (int k0 = 0; k0 < INF; k0 += 8) {
        As[lk4 + 0][lrow] = av.x; As[lk4 + 1][lrow] = av.y;
        As[lk4 + 2][lrow] = av.z; As[lk4 + 3][lrow] = av.w;
        Bs[lk4 + 0][lrow] = bv.x; Bs[lk4 + 1][lrow] = bv.y;
        Bs[lk4 + 2][lrow] = bv.z; Bs[lk4 + 3][lrow] = bv.w;
        __syncthreads();
        if (k0 + 8 < INF) {
            av = *(const float4*)(Ap + k0 + 8);
            bv = *(const float4*)(Wp + k0 + 8);
        }
#pragma unroll
        for (int k = 0; k < 8; k++) {
            float a[8], bb[8];
            *(float4*)(a)      = *(const float4*)&As[k][ty * 8];
            *(float4*)(a + 4)  = *(const float4*)&As[k][ty * 8 + 4];
            *(float4*)(bb)     = *(const float4*)&Bs[k][tx * 8];
            *(float4*)(bb + 4) = *(const float4*)&Bs[k][tx * 8 + 4];
#pragma unroll
            for (int i = 0; i < 8; i++)
#pragma unroll
                for (int j = 0; j < 8; j++)
                    acc[i][j] = fmaf(a[i], bb[j], acc[i][j]);
        }
        __syncthreads();
    }

    const float* __restrict__ bih = dir ? bihr : bihf;
    const float* __restrict__ bhh = dir ? bhhr : bhhf;
    const int gcol = gbase + tx * 8;
    float bias[8];
#pragma unroll
    for (int j = 0; j < 8; j++) bias[j] = bih[gcol + j] + bhh[gcol + j];

    float* base = g_xg + (size_t)dir * CHSTRIDE;
#pragma unroll
    for (int i = 0; i < 8; i++) {
        int sloc = ty * 8 + i;
        float* dst = base + ((size_t)sloc * BDIM + b) * G4 + gcol;
        float4 v0, v1;
        v0.x = acc[i][0] + bias[0]; v0.y = acc[i][1] + bias[1];
        v0.z = acc[i][2] + bias[2]; v0.w = acc[i][3] + bias[3];
        v1.x = acc[i][4] + bias[4]; v1.y = acc[i][5] + bias[5];
        v1.z = acc[i][6] + bias[6]; v1.w = acc[i][7] + bias[7];
        *(float4*)dst       = v0;
        *(float4*)(dst + 4) = v1;
    }
}

// ---------------------------------------------------------------------------
// Kernel 2: persistent bidirectional LSTM recurrence for one chunk.
// 128 CTAs x 256 threads, 1 CTA/SM (135 KB smem), single wave on 148 SMs.
// CTAs 0..63 -> forward (8 hidden units each), 64..127 -> reverse.
// W_hh slice in smem; c-state persisted in g_cbuf across chunk launches;
// h exchanged via g_hbuf each step with a global atomic barrier.
// ---------------------------------------------------------------------------
#define RCTAS 128
#define UPC   8
#define SMEM_REC ((16384 + 16384 + 8 * 132) * 4)

__device__ __forceinline__ void grid_bar(unsigned target) {
    __syncthreads();
    if (threadIdx.x == 0) {
        __threadfence();
        atomicAdd(&g_bar, 1u);
        while (*((volatile unsigned*)&g_bar) < target) __nanosleep(64);
        __threadfence();
    }
    __syncthreads();
}

__device__ __forceinline__ float sigf(float x) {
    return 1.0f / (1.0f + __expf(-x));
}

__global__ void __launch_bounds__(256, 1) lstm_recur(
    const float* __restrict__ whh_f, const float* __restrict__ whh_r,
    const int* __restrict__ sizes, int chunk)
{
    extern __shared__ float sm[];
    float* w_s = sm;                 // [UPC][4][512]          16384 floats
    float* h_s = sm + 16384;         // [kc=128][b=32][4]      16384 floats
    float* x_s = sm + 32768;         // [UPC][132] staging / exchange

    const int cta = blockIdx.x;
    const int dir = cta >> 6;
    const int u0  = (cta & 63) * UPC;
    const float* __restrict__ Whh = dir ? whh_r : whh_f;

    const int tid  = threadIdx.x;
    const int warp = tid >> 5, lane = tid & 31;

    // Load persistent W_hh slice: w_s[u][gate][k], g = gate*512 + (u0+u)
    for (int i = tid; i < 4096; i += 256) {
        int idx = i << 2;
        int u    = idx >> 11;
        int rem  = idx & 2047;
        int gate = rem >> 9;
        int k    = rem & 511;
        *(float4*)(w_s + idx) =
            *(const float4*)(Whh + ((size_t)(gate * 512 + u0 + u)) * HID + k);
    }

    const int mylen = sizes[lane] >> 1;   // lane == batch in pointwise phase
    const int gate = lane >> 3;
    const int b0   = (lane & 7) << 2;
    const float* wrow = w_s + (warp * 4 + gate) * 512;
    const float* xgbase = g_xg + (size_t)dir * CHSTRIDE;
    float* hglob = g_hbuf + dir * 16384;
    const int ug = u0 + warp;

    // persisted cell state for cell (ug, lane)
    float c_state = g_cbuf[dir * 16384 + ug * 32 + lane];

    __syncthreads();   // w_s ready

    for (int sloc = 0; sloc < CHUNK; ++sloc) {
        const int s = chunk * CHUNK + sloc;

        // cooperative load of full h (same layout copy)
        {
            const float4* src = (const float4*)hglob;
            float4* dst = (float4*)h_s;
#pragma unroll
            for (int i = 0; i < 16; i++) dst[tid + i * 256] = src[tid + i * 256];
        }
        // stage this CTA's x-gate slice: x_s[u][gate*33 + b]
        if (tid < 128) {
            int b = tid >> 2, gt = tid & 3;
            const float* p = xgbase + ((size_t)sloc * BDIM + b) * G4 + gt * 512 + u0;
            float4 v0 = *(const float4*)p;
            float4 v1 = *(const float4*)(p + 4);
            x_s[0 * 132 + gt * 33 + b] = v0.x;
            x_s[1 * 132 + gt * 33 + b] = v0.y;
            x_s[2 * 132 + gt * 33 + b] = v0.z;
            x_s[3 * 132 + gt * 33 + b] = v0.w;
            x_s[4 * 132 + gt * 33 + b] = v1.x;
            x_s[5 * 132 + gt * 33 + b] = v1.y;
            x_s[6 * 132 + gt * 33 + b] = v1.z;
            x_s[7 * 132 + gt * 33 + b] = v1.w;
        }
        __syncthreads();

        // matmul phase: lane computes gate `gate` for batches b0..b0+3 of unit ug
        float a0 = x_s[warp * 132 + gate * 33 + b0 + 0];
        float a1 = x_s[warp * 132 + gate * 33 + b0 + 1];
        float a2 = x_s[warp * 132 + gate * 33 + b0 + 2];
        float a3 = x_s[warp * 132 + gate * 33 + b0 + 3];
#pragma unroll 8
        for (int kc = 0; kc < 128; kc++) {
            float4 w4 = *(const float4*)(wrow + kc * 4);
            const float* hb = h_s + kc * 128;
            float4 h0 = *(const float4*)(hb + (b0 + 0) * 4);
            float4 h1 = *(const float4*)(hb + (b0 + 1) * 4);
            float4 h2 = *(const float4*)(hb + (b0 + 2) * 4);
            float4 h3 = *(const float4*)(hb + (b0 + 3) * 4);
            a0 = fmaf(w4.x, h0.x, a0); a1 = fmaf(w4.x, h1.x, a1);
            a2 = fmaf(w4.x, h2.x, a2); a3 = fmaf(w4.x, h3.x, a3);
            a0 = fmaf(w4.y, h0.y, a0); a1 = fmaf(w4.y, h1.y, a1);
            a2 = fmaf(w4.y, h2.y, a2); a3 = fmaf(w4.y, h3.y, a3);
            a0 = fmaf(w4.z, h0.z, a0); a1 = fmaf(w4.z, h1.z, a1);
            a2 = fmaf(w4.z, h2.z, a2); a3 = fmaf(w4.z, h3.z, a3);
            a0 = fmaf(w4.w, h0.w, a0); a1 = fmaf(w4.w, h1.w, a1);
            a2 = fmaf(w4.w, h2.w, a2); a3 = fmaf(w4.w, h3.w, a3);
        }

        // gate exchange within warp (reuse this warp's private x_s row)
        float* ex = x_s + warp * 132;
        ex[gate * 32 + b0 + 0] = a0;
        ex[gate * 32 + b0 + 1] = a1;
        ex[gate * 32 + b0 + 2] = a2;
        ex[gate * 32 + b0 + 3] = a3;
        __syncwarp();

        // pointwise phase: lane == batch b, cell (ug, lane)
        float xi = ex[0 * 32 + lane];
        float xf = ex[1 * 32 + lane];
        float xg = ex[2 * 32 + lane];
        float xo = ex[3 * 32 + lane];

        if (s < mylen) {
            float i_ = sigf(xi);
            float f_ = sigf(xf);
            float gg = tanhf(xg);
            float o_ = sigf(xo);
            c_state = f_ * c_state + i_ * gg;
            float hnew = o_ * tanhf(c_state);
            hglob[(ug >> 2) * 128 + lane * 4 + (ug & 3)] = hnew;
            int tout = dir ? (mylen - 1 - s) : s;
            g_out[((size_t)lane * TP + tout) * 1024 + dir * 512 + ug] = hnew;
        }

        grid_bar((unsigned)(chunk * CHUNK + sloc + 1) * RCTAS);
    }

    // persist cell state for next chunk
    g_cbuf[dir * 16384 + ug * 32 + lane] = c_state;
}

// ---------------------------------------------------------------------------
// Kernel 3: projection GEMM  out[m][p] = tanh( g_out[m][:] . proj_w[p][:] + pb )
// ---------------------------------------------------------------------------
__global__ void __launch_bounds__(256) proj_gemm(
    const float* __restrict__ Wp_, const float* __restrict__ pb,
    float* __restrict__ out)
{
    __shared__ float As[8][128];
    __shared__ float Bs[8][128];

    const int n0 = blockIdx.x * 128;          // P=512 -> 4 tiles
    const int m0 = blockIdx.y * 128;

    const int tid  = threadIdx.x;
    const int lrow = tid >> 1;
    const int lk4  = (tid & 1) << 2;
    const float* Ap = g_out + (size_t)(m0 + lrow) * 1024 + lk4;
    const float* Wp = Wp_ + (size_t)(n0 + lrow) * 1024 + lk4;

    const int tx = tid & 15, ty = tid >> 4;

    float acc[8][8];
#pragma unroll
    for (int i = 0; i < 8; i++)
#pragma unroll
        for (int j = 0; j < 8; j++) acc[i][j] = 0.0f;

    float4 av = *(const float4*)Ap;
    float4 bv = *(const float4*)Wp;

    for (int k0 = 0; k0 < 1024; k0 += 8) {
        As[lk4 + 0][lrow] = av.x; As[lk4 + 1][lrow] = av.y;
        As[lk4 + 2][lrow] = av.z; As[lk4 + 3][lrow] = av.w;
        Bs[lk4 + 0][lrow] = bv.x; Bs[lk4 + 1][lrow] = bv.y;
        Bs[lk4 + 2][lrow] = bv.z; Bs[lk4 + 3][lrow] = bv.w;
        __syncthreads();
        if (k0 + 8 < 1024) {
            av = *(const float4*)(Ap + k0 + 8);
            bv = *(const float4*)(Wp + k0 + 8);
        }
#pragma unroll
        for (int k = 0; k < 8; k++) {
            float a[8], bb[8];
            *(float4*)(a)      = *(const float4*)&As[k][ty * 8];
            *(float4*)(a + 4)  = *(const float4*)&As[k][ty * 8 + 4];
            *(float4*)(bb)     = *(const float4*)&Bs[k][tx * 8];
            *(float4*)(bb + 4) = *(const float4*)&Bs[k][tx * 8 + 4];
#pragma unroll
            for (int i = 0; i < 8; i++)
#pragma unroll
                for (int j = 0; j < 8; j++)
                    acc[i][j] = fmaf(a[i], bb[j], acc[i][j]);
        }
        __syncthreads();
    }

    const int pcol = n0 + tx * 8;
    float bias[8];
#pragma unroll
    for (int j = 0; j < 8; j++) bias[j] = pb[pcol + j];

#pragma unroll
    for (int i = 0; i < 8; i++) {
        int m = m0 + ty * 8 + i;
        float* dst = out + (size_t)m * PDIM + pcol;
        float4 v0, v1;
        v0.x = tanhf(acc[i][0] + bias[0]); v0.y = tanhf(acc[i][1] + bias[1]);
        v0.z = tanhf(acc[i][2] + bias[2]); v0.w = tanhf(acc[i][3] + bias[3]);
        v1.x = tanhf(acc[i][4] + bias[4]); v1.y = tanhf(acc[i][5] + bias[5]);
        v1.z = tanhf(acc[i][6] + bias[6]); v1.w = tanhf(acc[i][7] + bias[7]);
        *(float4*)dst       = v0;
        *(float4*)(dst + 4) = v1;
    }
}

// Optional second output: lens = input_size // 2 (if harness flattens the tuple)
__global__ void lens_tail(const int* __restrict__ sizes, float* __restrict__ out,
                          int extra) {
    int i = threadIdx.x;
    if (i < extra && i < BDIM)
        out[(size_t)MROWS * PDIM + i] = (float)(sizes[i] >> 1);
}

// ---------------------------------------------------------------------------
extern "C" void kernel_launch(void* const* d_in, const int* in_sizes, int n_in,
                              void* d_out, int out_size) {
    const float* x    = (const float*)d_in[0];
    const int*   sz   = (const int*)d_in[1];
    const float* wihf = (const float*)d_in[2];
    const float* whhf = (const float*)d_in[3];
    const float* bihf = (const float*)d_in[4];
    const float* bhhf = (const float*)d_in[5];
    const float* wihr = (const float*)d_in[6];
    const float* whhr = (const float*)d_in[7];
    const float* bihr = (const float*)d_in[8];
    const float* bhhr = (const float*)d_in[9];
    const float* pw   = (const float*)d_in[10];
    const float* pbv  = (const float*)d_in[11];
    float* out = (float*)d_out;

    cudaFuncSetAttribute(lstm_recur, cudaFuncAttributeMaxDynamicSharedMemorySize,
                         SMEM_REC);

    zero_scratch<<<512, 256>>>();
    for (int c = 0; c < NCH; ++c) {
        gates_gemm<<<dim3(32, 32), 256>>>(x, wihf, wihr, bihf, bhhf, bihr, bhhr,
                                          sz, c);
        lstm_recur<<<RCTAS, 256, SMEM_REC>>>(whhf, whhr, sz, c);
    }
    proj_gemm<<<dim3(4, 256), 256>>>(pw, pbv, out);

    long long extra = (long long)out_size - (long long)MROWS * PDIM;
    if (extra > 0) lens_tail<<<1, 32>>>(sz, out, (int)extra);
}